// round 5
// baseline (speedup 1.0000x reference)
#include <cuda_runtime.h>
#include <cuda_fp16.h>
#include <math.h>

#define N 4096
#define LOG16   2.772588722239781f    // log(16)
#define LOG_CU  13.862943611198906f   // log(2^20)
#define F_SCALE 1048576.0f            // 2^20
#define NBLOCKS 256
#define NTHREADS 256
#define NITER 10
#define CPB 2048                      // columns per block (2-way split)
#define NSTAGES 8
#define STAGE_COLS 256
#define A_STRIDE 528                  // bytes per K-row in smem stage (conflict-free ldmatrix)
#define A_BUF (32 * A_STRIDE)         // 16896 B per stage buffer
#define V_STRIDE_H 2056               // halves per V row (4112 B, conflict-free B loads)
#define SMEM_V (8 * V_STRIDE_H * 2)   // 32896
#define SMEM_A_OFF SMEM_V
#define SMEM_RED_OFF (SMEM_V + 2 * A_BUF)        // 66688
#define SMEM_TOTAL (SMEM_RED_OFF + 8 * 16 * 4 * 4)  // 68736

// Scratch (allocation-free rule: __device__ globals)
__device__ __half g_K [(size_t)N * N];   // 16*exp(-C/eps), row-major
__device__ __half g_KT[(size_t)N * N];   // transpose
__device__ float  g_pu[2 * N * 4];       // u-direction partials [chunk][row][s]
__device__ float  g_pv[2 * N * 4];       // v-direction partials
__device__ unsigned long long g_count;   // grid-barrier generation counter

// ---------------------------------------------------------------------------
// Software grid barrier: monotonic generation counter (graph-replay safe)
// ---------------------------------------------------------------------------
__device__ __forceinline__ void grid_sync() {
    __syncthreads();
    if (threadIdx.x == 0) {
        unsigned long long gen;
        asm volatile("atom.add.release.gpu.u64 %0, [%1], 1;"
                     : "=l"(gen) : "l"(&g_count) : "memory");
        unsigned long long target =
            (gen / NBLOCKS + 1ull) * (unsigned long long)NBLOCKS;
        unsigned long long cur;
        do {
            asm volatile("ld.acquire.gpu.u64 %0, [%1];"
                         : "=l"(cur) : "l"(&g_count) : "memory");
        } while (cur < target);
    }
    __syncthreads();
}

// ---------------------------------------------------------------------------
// Precompute K = 16*exp(-C/eps) and its transpose
// ---------------------------------------------------------------------------
__global__ void exp_transpose_kernel(const float* __restrict__ C,
                                     const float* __restrict__ epsp) {
    __shared__ __half tile[32][33];
    const float inv_eps = 1.0f / *epsp;
    const int tx = threadIdx.x, ty = threadIdx.y;
    const int bx = blockIdx.x << 5, by = blockIdx.y << 5;

#pragma unroll
    for (int k = 0; k < 4; ++k) {
        int r = by + ty + (k << 3);
        float c = C[(size_t)r * N + bx + tx];
        __half h = __float2half_rn(__expf(LOG16 - c * inv_eps));
        g_K[(size_t)r * N + bx + tx] = h;
        tile[ty + (k << 3)][tx] = h;
    }
    __syncthreads();
#pragma unroll
    for (int k = 0; k < 4; ++k) {
        int m = bx + ty + (k << 3);
        g_KT[(size_t)m * N + by + tx] = tile[tx][ty + (k << 3)];
    }
}

// ---------------------------------------------------------------------------
// Persistent tensor-core Sinkhorn. 256 blocks x 256 threads (8 warps).
// Block = 32 rows x 2048 cols (blockIdx = rowTile*2 + chunk).
// Warp w: row-tile rt=w>>2 (16 rows), k-quarter q=w&3 (512 cols).
// Per pass: 8 double-buffered cp.async stages of 32x256 fp16 K-tile,
// ldmatrix.x4 -> mma.sync.m16n8k16 against fp16 V[n][k] held in smem.
// ---------------------------------------------------------------------------
__global__ void __launch_bounds__(NTHREADS, 2)
sinkhorn_persistent_kernel(const float* __restrict__ alpha,
                           const float* __restrict__ beta,
                           const float* __restrict__ epsp,
                           float* __restrict__ out) {
    extern __shared__ char smem[];
    __half* Vs  = (__half*)smem;
    char*   Abuf = smem + SMEM_A_OFF;
    float*  red  = (float*)(smem + SMEM_RED_OFF);

    const int tid  = threadIdx.x;
    const int warp = tid >> 5;
    const int lane = tid & 31;
    const int rowT  = blockIdx.x >> 1;
    const int chunk = blockIdx.x & 1;
    const int row0  = rowT * 32;
    const int colBase = chunk * CPB;
    const int rt = warp >> 2;
    const int q  = warp & 3;

    const unsigned sA = (unsigned)__cvta_generic_to_shared(Abuf);
    const unsigned sV = (unsigned)__cvta_generic_to_shared(Vs);

    // zero V rows 4..7 once (N-padding of the mma B operand)
    for (int i = tid; i < 4 * V_STRIDE_H; i += NTHREADS)
        Vs[4 * V_STRIDE_H + i] = __float2half_rn(0.f);

    // cp.async copy mapping: thread -> (row, 64B segment)
    const int crow = tid >> 3;
    const int cseg = tid & 7;
    const unsigned dstbase = sA + crow * A_STRIDE + cseg * 64;

    // ldmatrix.x4 lane address: groups of 8 lanes -> 4 8x8 tiles of 16x16 A
    const int gg   = lane >> 3;
    const int arow = 16 * rt + (gg & 1) * 8 + (lane & 7);
    const unsigned abase = sA + arow * A_STRIDE + (gg >> 1) * 16;
    // B fragment base: n = lane>>2, k-pair offset = (lane&3)*4 bytes
    const unsigned bbase = sV + (lane >> 2) * (V_STRIDE_H * 2) + (lane & 3) * 4;

    for (int it = 0; it < 2 * NITER; ++it) {
        const __half* M    = (it & 1) ? g_KT : g_K;
        float*        pout = (it & 1) ? g_pv : g_pu;

        // ---- stage V (fp16, [n][k], divide fused; F_SCALE keeps fp16 normal) ----
        if (it == 0) {
            const __half one = __float2half_rn(1.f);
            for (int i = tid; i < CPB; i += NTHREADS) {
                Vs[0 * V_STRIDE_H + i] = one;
                Vs[1 * V_STRIDE_H + i] = one;
                Vs[2 * V_STRIDE_H + i] = one;
                Vs[3 * V_STRIDE_H + i] = one;
            }
        } else {
            const float*  num  = (it & 1) ? alpha : beta;
            const float4* part = (const float4*)((it & 1) ? g_pu : g_pv);
            for (int i = tid; i < CPB; i += NTHREADS) {
                int col = colBase + i;
                float4 p0 = __ldcg(part + col);
                float4 p1 = __ldcg(part + N + col);
                Vs[0 * V_STRIDE_H + i] = __float2half_rn(
                    __fdividef(F_SCALE * __ldg(num + 0 * N + col), p0.x + p1.x));
                Vs[1 * V_STRIDE_H + i] = __float2half_rn(
                    __fdividef(F_SCALE * __ldg(num + 1 * N + col), p0.y + p1.y));
                Vs[2 * V_STRIDE_H + i] = __float2half_rn(
                    __fdividef(F_SCALE * __ldg(num + 2 * N + col), p0.z + p1.z));
                Vs[3 * V_STRIDE_H + i] = __float2half_rn(
                    __fdividef(F_SCALE * __ldg(num + 3 * N + col), p0.w + p1.w));
            }
        }
        __syncthreads();

        const char* gbase = (const char*)(M + (size_t)row0 * N + colBase)
                          + (size_t)crow * (N * 2) + cseg * 64;

        // prologue: stage 0
        {
            const char* src = gbase;
            unsigned dst = dstbase;
#pragma unroll
            for (int u = 0; u < 4; ++u)
                asm volatile("cp.async.cg.shared.global [%0], [%1], 16;"
                             :: "r"(dst + u * 16), "l"(src + u * 16) : "memory");
            asm volatile("cp.async.commit_group;" ::: "memory");
        }

        float d0 = 0.f, d1 = 0.f, d2 = 0.f, d3 = 0.f;

#pragma unroll
        for (int s = 0; s < NSTAGES; ++s) {
            if (s + 1 < NSTAGES) {
                const char* src = gbase + (s + 1) * (STAGE_COLS * 2);
                unsigned dst = dstbase + ((s + 1) & 1) * A_BUF;
#pragma unroll
                for (int u = 0; u < 4; ++u)
                    asm volatile("cp.async.cg.shared.global [%0], [%1], 16;"
                                 :: "r"(dst + u * 16), "l"(src + u * 16) : "memory");
                asm volatile("cp.async.commit_group;" ::: "memory");
                asm volatile("cp.async.wait_group 1;" ::: "memory");
            } else {
                asm volatile("cp.async.wait_group 0;" ::: "memory");
            }
            __syncthreads();

            const unsigned abufsel = abase + (s & 1) * A_BUF;
#pragma unroll
            for (int j = 0; j < 4; ++j) {
                const int colb = (64 * q + 16 * j) * 2;   // byte col within stage row
                unsigned a0, a1, a2, a3;
                asm volatile("ldmatrix.sync.aligned.m8n8.x4.shared.b16 {%0,%1,%2,%3}, [%4];"
                             : "=r"(a0), "=r"(a1), "=r"(a2), "=r"(a3)
                             : "r"(abufsel + colb));
                const int kloc = s * STAGE_COLS + 64 * q + 16 * j;
                unsigned b0, b1;
                asm volatile("ld.shared.b32 %0, [%1];" : "=r"(b0) : "r"(bbase + kloc * 2));
                asm volatile("ld.shared.b32 %0, [%1];" : "=r"(b1) : "r"(bbase + kloc * 2 + 16));
                asm volatile("mma.sync.aligned.m16n8k16.row.col.f32.f16.f16.f32 "
                             "{%0,%1,%2,%3}, {%4,%5,%6,%7}, {%8,%9}, {%0,%1,%2,%3};"
                             : "+f"(d0), "+f"(d1), "+f"(d2), "+f"(d3)
                             : "r"(a0), "r"(a1), "r"(a2), "r"(a3), "r"(b0), "r"(b1));
            }
            __syncthreads();
        }

        // ---- epilogue: C fragments (cols 0-3 useful) -> smem -> q-reduction ----
        if ((lane & 3) < 2) {
            const int c = 2 * (lane & 3);
            const int r = lane >> 2;
            red[(warp * 16 + r) * 4 + c]     = d0;
            red[(warp * 16 + r) * 4 + c + 1] = d1;
            red[(warp * 16 + r + 8) * 4 + c]     = d2;
            red[(warp * 16 + r + 8) * 4 + c + 1] = d3;
        }
        __syncthreads();
        if (tid < 128) {
            const int rt2 = tid >> 6, row = (tid >> 2) & 15, c = tid & 3;
            float v = red[((4 * rt2 + 0) * 16 + row) * 4 + c]
                    + red[((4 * rt2 + 1) * 16 + row) * 4 + c]
                    + red[((4 * rt2 + 2) * 16 + row) * 4 + c]
                    + red[((4 * rt2 + 3) * 16 + row) * 4 + c];
            __stcg(pout + (size_t)chunk * N * 4
                        + (size_t)(row0 + 16 * rt2 + row) * 4 + c, v);
        }
        grid_sync();
    }

    // ---- finalize:  y_u = 16*(Kv) -> f = eps*(log a - log y_u + log16)
    //                 y_v = 16*2^16*(KTu) -> g = eps*(log b - log y_v + log 2^20)
    int n = blockIdx.x * NTHREADS + tid;
    if (n < N) {
        const float eps = *epsp;
        const float4* pu = (const float4*)g_pu;
        const float4* pv = (const float4*)g_pv;
        float4 u0 = __ldcg(pu + n), u1 = __ldcg(pu + N + n);
        float4 v0 = __ldcg(pv + n), v1 = __ldcg(pv + N + n);
        out[0 * N + n] = eps * (logf(alpha[0 * N + n]) - logf(u0.x + u1.x) + LOG16);
        out[1 * N + n] = eps * (logf(alpha[1 * N + n]) - logf(u0.y + u1.y) + LOG16);
        out[2 * N + n] = eps * (logf(alpha[2 * N + n]) - logf(u0.z + u1.z) + LOG16);
        out[3 * N + n] = eps * (logf(alpha[3 * N + n]) - logf(u0.w + u1.w) + LOG16);
        float* og = out + 4 * N;
        og[0 * N + n] = eps * (logf(beta[0 * N + n]) - logf(v0.x + v1.x) + LOG_CU);
        og[1 * N + n] = eps * (logf(beta[1 * N + n]) - logf(v0.y + v1.y) + LOG_CU);
        og[2 * N + n] = eps * (logf(beta[2 * N + n]) - logf(v0.z + v1.z) + LOG_CU);
        og[3 * N + n] = eps * (logf(beta[3 * N + n]) - logf(v0.w + v1.w) + LOG_CU);
    }
}

// ---------------------------------------------------------------------------
extern "C" void kernel_launch(void* const* d_in, const int* in_sizes, int n_in,
                              void* d_out, int out_size) {
    const float* alpha = (const float*)d_in[0];
    const float* beta  = (const float*)d_in[1];
    const float* C     = (const float*)d_in[2];
    const float* eps   = (const float*)d_in[3];
    float* out = (float*)d_out;

    cudaFuncSetAttribute(sinkhorn_persistent_kernel,
                         cudaFuncAttributeMaxDynamicSharedMemorySize, SMEM_TOTAL);

    exp_transpose_kernel<<<dim3(128, 128), dim3(32, 8)>>>(C, eps);
    sinkhorn_persistent_kernel<<<NBLOCKS, NTHREADS, SMEM_TOTAL>>>(alpha, beta, eps, out);
}